// round 14
// baseline (speedup 1.0000x reference)
#include <cuda_runtime.h>
#include <cuda_bf16.h>
#include <cstdint>
#include <stdint.h>
#include <math.h>

#define NN 50000
#define EE 800000
#define DIN 128
#define H1 256
#define H2 128
#define NG 64
#define SCAN_BLKS 196

// ---------------- device scratch (static, allocation-free) ----------------
__device__ int   g_deg[NN];
__device__ int   g_rowptr[NN + 1];   // LOCAL (per-256-block) exclusive scan; +g_boff[blk] = absolute
__device__ int   g_cur[NN];          // local cursor; +g_boff at use
__device__ int   g_csrc[EE];
__device__ int   g_bsum[256];
__device__ int   g_boff[256];

// bf16-split activation buffers
__device__ __nv_bfloat16 g_A0h[NN * 256];   // cols 0-127: mean0, 128-255: x
__device__ __nv_bfloat16 g_A0l[NN * 256];
__device__ __nv_bfloat16 g_Hh[NN * 256];    // h (layer-0 output)
__device__ __nv_bfloat16 g_Hl[NN * 256];

// bf16-split weights (prepped each call), [K][N] row-major
__device__ __nv_bfloat16 g_W0h[256 * 256];
__device__ __nv_bfloat16 g_W0l[256 * 256];
__device__ __nv_bfloat16 g_Wp0h[128 * 256];
__device__ __nv_bfloat16 g_Wp0l[128 * 256];
__device__ __nv_bfloat16 g_W1h[256 * 384];
__device__ __nv_bfloat16 g_W1l[256 * 384];
__device__ float g_bias1[384];

// fp32 intermediates
__device__ float g_out0[NN * H1];
__device__ float g_res0[NN * H1];
__device__ float g_rn0[NN];          // per-row inv L2 norm of out0
__device__ float g_tuw[NN * 384];   // 0-127: t, 128-255: u, 256-383: res1
__device__ float g_out1[NN * H2];
__device__ float g_sum0[H1];
__device__ float g_sq0[H1];
__device__ float g_sum1[H2];
__device__ float g_sq1[H2];
__device__ float g_a0[H1];
__device__ float g_b0[H1];
__device__ float g_embsum[NG * H2];
__device__ float g_gcnt[NG];

__device__ __forceinline__ void split_bf16(float v, __nv_bfloat16& h, __nv_bfloat16& l) {
    h = __float2bfloat16(v);
    l = __float2bfloat16(v - __bfloat162float(h));
}

__device__ __forceinline__ void store_split4(const float* v, __nv_bfloat16* ph, __nv_bfloat16* pl) {
    union { __nv_bfloat16 b[4]; uint2 u; } Hh, Ll;
#pragma unroll
    for (int k = 0; k < 4; k++) split_bf16(v[k], Hh.b[k], Ll.b[k]);
    *reinterpret_cast<uint2*>(ph) = Hh.u;
    *reinterpret_cast<uint2*>(pl) = Ll.u;
}

// ---------------- init ----------------
__global__ void k_zero() {
    int i = blockIdx.x * blockDim.x + threadIdx.x;
    int stride = gridDim.x * blockDim.x;
    for (int t = i; t < NN; t += stride) g_deg[t] = 0;
    for (int t = i; t < H1; t += stride) { g_sum0[t] = 0.f; g_sq0[t] = 0.f; }
    for (int t = i; t < H2; t += stride) { g_sum1[t] = 0.f; g_sq1[t] = 0.f; }
    for (int t = i; t < NG * H2; t += stride) g_embsum[t] = 0.f;
    for (int t = i; t < NG; t += stride) g_gcnt[t] = 0.f;
}

// fused: edge-dst degree count + per-graph node count + weight prep
__global__ void k_combo(const int* __restrict__ ei, const int* __restrict__ batch,
                        const float* __restrict__ Wl0, const float* __restrict__ Wr0,
                        const float* __restrict__ Wp0,
                        const float* __restrict__ Wl1, const float* __restrict__ Wr1,
                        const float* __restrict__ Wp1,
                        const float* __restrict__ bl1, const float* __restrict__ bp1) {
    const int* dst = ei + EE;
    int i = blockIdx.x * blockDim.x + threadIdx.x;
    int stride = gridDim.x * blockDim.x;
    for (int e = i; e < EE; e += stride) atomicAdd(&g_deg[dst[e]], 1);
    for (int t = i; t < NN; t += stride) atomicAdd(&g_gcnt[batch[t]], 1.f);

    const int T0 = 256 * 256;
    const int T1 = 128 * 256;
    const int T2 = 256 * 384;
    for (int t = i; t < T0 + T1 + T2; t += stride) {
        if (t < T0) {
            int r = t >> 8;
            int c = t & 255;
            float v = (r < 128) ? Wl0[r * 256 + c] : Wr0[(r - 128) * 256 + c];
            split_bf16(v, g_W0h[t], g_W0l[t]);
        } else if (t < T0 + T1) {
            int j = t - T0;
            split_bf16(Wp0[j], g_Wp0h[j], g_Wp0l[j]);
        } else {
            int j = t - T0 - T1;
            int r = j / 384;
            int c = j % 384;
            float v;
            if (c < 128) v = Wl1[r * 128 + c];
            else if (c < 256) v = Wr1[r * 128 + (c - 128)];
            else v = Wp1[r * 128 + (c - 256)];
            split_bf16(v, g_W1h[j], g_W1l[j]);
        }
    }
    for (int t = i; t < 384; t += stride) {
        float v;
        if (t < 128) v = 0.f;
        else if (t < 256) v = bl1[t - 128];
        else v = bp1[t - 256];
        g_bias1[t] = v;
    }
}

// per-block exclusive scan of deg; writes LOCAL excl to rowptr AND cur; block totals to g_bsum
__global__ void k_scan_a() {
    __shared__ int ws[8];
    int tid = threadIdx.x;
    int lane = tid & 31;
    int w = tid >> 5;
    int idx = blockIdx.x * 256 + tid;
    int v = (idx < NN) ? g_deg[idx] : 0;
    int s = v;
#pragma unroll
    for (int o = 1; o < 32; o <<= 1) {
        int n = __shfl_up_sync(0xffffffffu, s, o);
        if (lane >= o) s += n;
    }
    if (lane == 31) ws[w] = s;
    __syncthreads();
    if (tid < 8) {
        int t = ws[tid];
#pragma unroll
        for (int o = 1; o < 8; o <<= 1) {
            int n = __shfl_up_sync(0xffu, t, o);
            if (tid >= o) t += n;
        }
        ws[tid] = t;
    }
    __syncthreads();
    int incl = s + (w > 0 ? ws[w - 1] : 0);
    int excl = incl - v;
    if (idx < NN) {
        g_rowptr[idx] = excl;
        g_cur[idx] = excl;
    }
    if (tid == 255) g_bsum[blockIdx.x] = incl;
}

// scan block totals -> g_boff
__global__ void k_scan_b() {
    __shared__ int ws[8];
    int tid = threadIdx.x;
    int lane = tid & 31;
    int w = tid >> 5;
    int v = (tid < SCAN_BLKS) ? g_bsum[tid] : 0;
    int s = v;
#pragma unroll
    for (int o = 1; o < 32; o <<= 1) {
        int n = __shfl_up_sync(0xffffffffu, s, o);
        if (lane >= o) s += n;
    }
    if (lane == 31) ws[w] = s;
    __syncthreads();
    if (tid < 8) {
        int t = ws[tid];
#pragma unroll
        for (int o = 1; o < 8; o <<= 1) {
            int n = __shfl_up_sync(0xffu, t, o);
            if (tid >= o) t += n;
        }
        ws[tid] = t;
    }
    __syncthreads();
    int incl = s + (w > 0 ? ws[w - 1] : 0);
    if (tid < SCAN_BLKS) g_boff[tid] = incl - v;
    if (tid == SCAN_BLKS - 1) g_rowptr[NN] = v;
}

__global__ void k_fill(const int* __restrict__ ei) {
    const int* src = ei;
    const int* dst = ei + EE;
    int i = blockIdx.x * blockDim.x + threadIdx.x;
    int stride = gridDim.x * blockDim.x;
    for (int e = i; e < EE; e += stride) {
        int d = dst[e];
        int slot = atomicAdd(&g_cur[d], 1) + g_boff[d >> 8];
        g_csrc[slot] = src[e];
    }
}

// ---------------- aggregation (warp per node; rowptr is local + boff) ----------------
__global__ void k_agg0(const float* __restrict__ x) {
    int gw = (blockIdx.x * blockDim.x + threadIdx.x) >> 5;
    int lane = threadIdx.x & 31;
    int nw = (gridDim.x * blockDim.x) >> 5;
    for (int r = gw; r < NN; r += nw) {
        int s = g_rowptr[r] + g_boff[r >> 8];
        int e = g_rowptr[r + 1] + g_boff[(r + 1) >> 8];
        float4 acc = make_float4(0.f, 0.f, 0.f, 0.f);
        for (int p = s; p < e; p += 32) {
            int cnt = min(e - p, 32);
            int myidx = (lane < cnt) ? g_csrc[p + lane] : 0;
#pragma unroll 4
            for (int q = 0; q < cnt; q++) {
                int nbr = __shfl_sync(0xffffffffu, myidx, q);
                float4 xv = *reinterpret_cast<const float4*>(&x[nbr * DIN + lane * 4]);
                acc.x += xv.x; acc.y += xv.y; acc.z += xv.z; acc.w += xv.w;
            }
        }
        float inv = 1.f / (float)max(e - s, 1);
        float mv[4] = {acc.x * inv, acc.y * inv, acc.z * inv, acc.w * inv};
        store_split4(mv, &g_A0h[r * 256 + lane * 4], &g_A0l[r * 256 + lane * 4]);
        float4 xr = *reinterpret_cast<const float4*>(&x[r * DIN + lane * 4]);
        float xv4[4] = {xr.x, xr.y, xr.z, xr.w};
        store_split4(xv4, &g_A0h[r * 256 + 128 + lane * 4], &g_A0l[r * 256 + 128 + lane * 4]);
    }
}

// layer 1: aggregate t, add u, row L2-normalize -> out1; column stats fused
// (each lane owns columns lane*4..lane*4+3 of every row it emits).
__global__ void k_agg1() {
    int gw = (blockIdx.x * blockDim.x + threadIdx.x) >> 5;
    int lane = threadIdx.x & 31;
    int nw = (gridDim.x * blockDim.x) >> 5;
    float cs0 = 0.f, cs1 = 0.f, cs2 = 0.f, cs3 = 0.f;
    float cq0 = 0.f, cq1 = 0.f, cq2 = 0.f, cq3 = 0.f;
    for (int r = gw; r < NN; r += nw) {
        int s = g_rowptr[r] + g_boff[r >> 8];
        int e = g_rowptr[r + 1] + g_boff[(r + 1) >> 8];
        float4 acc = make_float4(0.f, 0.f, 0.f, 0.f);
        for (int p = s; p < e; p += 32) {
            int cnt = min(e - p, 32);
            int myidx = (lane < cnt) ? g_csrc[p + lane] : 0;
#pragma unroll 4
            for (int q = 0; q < cnt; q++) {
                int nbr = __shfl_sync(0xffffffffu, myidx, q);
                float4 tv = *reinterpret_cast<const float4*>(&g_tuw[nbr * 384 + lane * 4]);
                acc.x += tv.x; acc.y += tv.y; acc.z += tv.z; acc.w += tv.w;
            }
        }
        float invd = 1.f / (float)max(e - s, 1);
        float4 uv = *reinterpret_cast<const float4*>(&g_tuw[r * 384 + 128 + lane * 4]);
        float4 v;
        v.x = acc.x * invd + uv.x;
        v.y = acc.y * invd + uv.y;
        v.z = acc.z * invd + uv.z;
        v.w = acc.w * invd + uv.w;
        float q = v.x * v.x + v.y * v.y + v.z * v.z + v.w * v.w;
#pragma unroll
        for (int o = 16; o > 0; o >>= 1) q += __shfl_xor_sync(0xffffffffu, q, o);
        float inv = 1.f / fmaxf(sqrtf(q), 1e-12f);
        v.x *= inv; v.y *= inv; v.z *= inv; v.w *= inv;
        *reinterpret_cast<float4*>(&g_out1[r * H2 + lane * 4]) = v;
        cs0 += v.x; cq0 += v.x * v.x;
        cs1 += v.y; cq1 += v.y * v.y;
        cs2 += v.z; cq2 += v.z * v.z;
        cs3 += v.w; cq3 += v.w * v.w;
    }
    atomicAdd(&g_sum1[lane * 4 + 0], cs0);
    atomicAdd(&g_sum1[lane * 4 + 1], cs1);
    atomicAdd(&g_sum1[lane * 4 + 2], cs2);
    atomicAdd(&g_sum1[lane * 4 + 3], cs3);
    atomicAdd(&g_sq1[lane * 4 + 0], cq0);
    atomicAdd(&g_sq1[lane * 4 + 1], cq1);
    atomicAdd(&g_sq1[lane * 4 + 2], cq2);
    atomicAdd(&g_sq1[lane * 4 + 3], cq3);
}

// ---------------- bf16-split tensor-core GEMM (R5/R9, proven — UNTOUCHED) ----------------
#define A_ST 40
#define B_ST 136
#define A_STAGE_B (128 * A_ST * 2)
#define B_STAGE_B (32 * B_ST * 2)
#define SM_AL_OFF (2 * A_STAGE_B)
#define SM_BH_OFF (4 * A_STAGE_B)
#define SMEM_BYTES (SM_BH_OFF + 4 * B_STAGE_B)

__device__ __forceinline__ void cp16(unsigned int dst, const void* src, bool p) {
    int sz = p ? 16 : 0;
    asm volatile("cp.async.cg.shared.global [%0], [%1], 16, %2;\n"
                 :: "r"(dst), "l"(src), "r"(sz));
}
__device__ __forceinline__ void ldsm4(unsigned int* r, unsigned int a) {
    asm volatile("ldmatrix.sync.aligned.m8n8.x4.shared.b16 {%0,%1,%2,%3}, [%4];"
                 : "=r"(r[0]), "=r"(r[1]), "=r"(r[2]), "=r"(r[3]) : "r"(a));
}
__device__ __forceinline__ void ldsm4t(unsigned int* r, unsigned int a) {
    asm volatile("ldmatrix.sync.aligned.m8n8.x4.trans.shared.b16 {%0,%1,%2,%3}, [%4];"
                 : "=r"(r[0]), "=r"(r[1]), "=r"(r[2]), "=r"(r[3]) : "r"(a));
}
__device__ __forceinline__ void mma_bf16(float* d, const unsigned int* a, const unsigned int* b) {
    asm volatile("mma.sync.aligned.m16n8k16.row.col.f32.bf16.bf16.f32 "
                 "{%0,%1,%2,%3}, {%4,%5,%6,%7}, {%8,%9}, {%0,%1,%2,%3};"
                 : "+f"(d[0]), "+f"(d[1]), "+f"(d[2]), "+f"(d[3])
                 : "r"(a[0]), "r"(a[1]), "r"(a[2]), "r"(a[3]), "r"(b[0]), "r"(b[1]));
}

__device__ __forceinline__ void gemm_load_stage(
    unsigned int sbase, int tid, int row0, int k0, int stage,
    const __nv_bfloat16* Ah, const __nv_bfloat16* Al, int lda,
    const __nv_bfloat16* Bh, const __nv_bfloat16* Bl, int ldb, int col0)
{
#pragma unroll
    for (int i = 0; i < 2; i++) {
        int c = tid + i * 256;
        int row = c >> 2;
        int seg = c & 3;
        int gr = row0 + row;
        bool p = gr < NN;
        size_t goff = (size_t)(p ? gr : 0) * lda + k0 + seg * 8;
        unsigned int d = sbase + stage * A_STAGE_B + (unsigned int)(row * A_ST + seg * 8) * 2;
        cp16(d, Ah + goff, p);
        cp16(d + SM_AL_OFF, Al + goff, p);
    }
#pragma unroll
    for (int i = 0; i < 2; i++) {
        int c = tid + i * 256;
        int row = c >> 4;
        int seg = c & 15;
        size_t goff = (size_t)(k0 + row) * ldb + col0 + seg * 8;
        unsigned int d = sbase + SM_BH_OFF + stage * B_STAGE_B + (unsigned int)(row * B_ST + seg * 8) * 2;
        cp16(d, Bh + goff, true);
        cp16(d + 2 * B_STAGE_B, Bl + goff, true);
    }
    asm volatile("cp.async.commit_group;\n" ::: "memory");
}

// mode 0: out0  = A0 @ W0  (K=256, ldb=256, ldc=256)
// mode 1: res0  = x  @ Wp0 (K=128, ldb=256, ldc=256)
// mode 2: tuw   = H  @ W1  (K=256, ldb=384, ldc=384)
__global__ __launch_bounds__(256) void k_gemm_bf16(int mode, const float* __restrict__ bias_in) {
    extern __shared__ __align__(16) char sm[];
    const int tid = threadIdx.x;
    const int lane = tid & 31;
    const int warp = tid >> 5;
    const int wm = warp & 3;
    const int wn = warp >> 2;
    const int row0 = blockIdx.y * 128;
    const int col0 = blockIdx.x * 128;
    unsigned int sbase = (unsigned int)__cvta_generic_to_shared(sm);

    const __nv_bfloat16* Ah;
    const __nv_bfloat16* Al;
    const __nv_bfloat16* Bh;
    const __nv_bfloat16* Bl;
    const float* bias;
    float* C;
    int lda, ldb, ldc, K;
    if (mode == 0) {
        Ah = g_A0h; Al = g_A0l; lda = 256; K = 256;
        Bh = g_W0h; Bl = g_W0l; ldb = 256;
        bias = bias_in; C = g_out0; ldc = 256;
    } else if (mode == 1) {
        Ah = g_A0h + 128; Al = g_A0l + 128; lda = 256; K = 128;
        Bh = g_Wp0h; Bl = g_Wp0l; ldb = 256;
        bias = bias_in; C = g_res0; ldc = 256;
    } else {
        Ah = g_Hh; Al = g_Hl; lda = 256; K = 256;
        Bh = g_W1h; Bl = g_W1l; ldb = 384;
        bias = g_bias1; C = g_tuw; ldc = 384;
    }

    float acc[2][8][4];
#pragma unroll
    for (int i = 0; i < 2; i++) {
#pragma unroll
        for (int j = 0; j < 8; j++) {
#pragma unroll
            for (int q = 0; q < 4; q++) acc[i][j][q] = 0.f;
        }
    }

    const int S = K / 32;
    gemm_load_stage(sbase, tid, row0, 0, 0, Ah, Al, lda, Bh, Bl, ldb, col0);

    for (int s = 0; s < S; s++) {
        if (s + 1 < S) {
            gemm_load_stage(sbase, tid, row0, (s + 1) * 32, (s + 1) & 1, Ah, Al, lda, Bh, Bl, ldb, col0);
            asm volatile("cp.async.wait_group 1;\n" ::: "memory");
        } else {
            asm volatile("cp.async.wait_group 0;\n" ::: "memory");
        }
        __syncthreads();
        int stage = s & 1;
#pragma unroll
        for (int kk = 0; kk < 32; kk += 16) {
            unsigned int aH[2][4], aL[2][4];
#pragma unroll
            for (int mi = 0; mi < 2; mi++) {
                int r = wm * 32 + mi * 16 + (lane & 15);
                int cA = kk + ((lane >> 4) << 3);
                unsigned int ad = sbase + stage * A_STAGE_B + (unsigned int)(r * A_ST + cA) * 2;
                ldsm4(aH[mi], ad);
                ldsm4(aL[mi], ad + SM_AL_OFF);
            }
#pragma unroll
            for (int g = 0; g < 4; g++) {
                unsigned int bH[4], bL[4];
                int rB = kk + (lane & 15);
                int cB = wn * 64 + g * 16 + ((lane >> 4) << 3);
                unsigned int bd = sbase + SM_BH_OFF + stage * B_STAGE_B + (unsigned int)(rB * B_ST + cB) * 2;
                ldsm4t(bH, bd);
                ldsm4t(bL, bd + 2 * B_STAGE_B);
#pragma unroll
                for (int mi = 0; mi < 2; mi++) {
                    mma_bf16(acc[mi][2 * g], aH[mi], &bH[0]);
                    mma_bf16(acc[mi][2 * g], aL[mi], &bH[0]);
                    mma_bf16(acc[mi][2 * g], aH[mi], &bL[0]);
                    mma_bf16(acc[mi][2 * g + 1], aH[mi], &bH[2]);
                    mma_bf16(acc[mi][2 * g + 1], aL[mi], &bH[2]);
                    mma_bf16(acc[mi][2 * g + 1], aH[mi], &bL[2]);
                }
            }
        }
        __syncthreads();
    }

#pragma unroll
    for (int mi = 0; mi < 2; mi++) {
        int r0 = row0 + wm * 32 + mi * 16 + (lane >> 2);
#pragma unroll
        for (int nj = 0; nj < 8; nj++) {
            int c = col0 + wn * 64 + nj * 8 + 2 * (lane & 3);
            float b0 = bias[c];
            float b1 = bias[c + 1];
            if (r0 < NN) {
                float2 v = make_float2(acc[mi][nj][0] + b0, acc[mi][nj][1] + b1);
                *reinterpret_cast<float2*>(C + (size_t)r0 * ldc + c) = v;
            }
            if (r0 + 8 < NN) {
                float2 v = make_float2(acc[mi][nj][2] + b0, acc[mi][nj][3] + b1);
                *reinterpret_cast<float2*>(C + (size_t)(r0 + 8) * ldc + c) = v;
            }
        }
    }
}

// ---------------- row L2-norm + column stats (layer 0), warp per row ----------------
__global__ void k_norm_stats0() {
    __shared__ float ssum[256];
    __shared__ float ssq[256];
    int tid = threadIdx.x;
    int lane = tid & 31;
    int gw = (blockIdx.x * blockDim.x + tid) >> 5;
    int nw = (gridDim.x * blockDim.x) >> 5;
    ssum[tid] = 0.f;
    ssq[tid] = 0.f;
    __syncthreads();
    float s[8], q[8];
#pragma unroll
    for (int k = 0; k < 8; k++) { s[k] = 0.f; q[k] = 0.f; }
    for (int r = gw; r < NN; r += nw) {
        float4 v0 = *reinterpret_cast<const float4*>(&g_out0[r * H1 + lane * 8]);
        float4 v1 = *reinterpret_cast<const float4*>(&g_out0[r * H1 + lane * 8 + 4]);
        float t = v0.x * v0.x + v0.y * v0.y + v0.z * v0.z + v0.w * v0.w
                + v1.x * v1.x + v1.y * v1.y + v1.z * v1.z + v1.w * v1.w;
#pragma unroll
        for (int o = 16; o > 0; o >>= 1) t += __shfl_xor_sync(0xffffffffu, t, o);
        float inv = 1.f / fmaxf(sqrtf(t), 1e-12f);
        if (lane == 0) g_rn0[r] = inv;
        float v[8] = {v0.x * inv, v0.y * inv, v0.z * inv, v0.w * inv,
                      v1.x * inv, v1.y * inv, v1.z * inv, v1.w * inv};
#pragma unroll
        for (int k = 0; k < 8; k++) { s[k] += v[k]; q[k] += v[k] * v[k]; }
    }
#pragma unroll
    for (int k = 0; k < 8; k++) {
        atomicAdd(&ssum[lane * 8 + k], s[k]);
        atomicAdd(&ssq[lane * 8 + k], q[k]);
    }
    __syncthreads();
    atomicAdd(&g_sum0[tid], ssum[tid]);
    atomicAdd(&g_sq0[tid], ssq[tid]);
}

// bnprep for layer 0 only
__global__ void k_bnprep0(const float* __restrict__ g, const float* __restrict__ be) {
    int j = threadIdx.x;
    if (j < H1) {
        float mu = g_sum0[j] / (float)NN;
        float var = g_sq0[j] / (float)NN - mu * mu;
        float s = g[j] * rsqrtf(var + 1e-5f);
        g_a0[j] = s;
        g_b0[j] = be[j] - mu * s;
    }
}

// BN + relu + residual layer 0; applies row inv-norm from g_rn0 on the fly.
__global__ void k_bnapply0() {
    int i = blockIdx.x * blockDim.x + threadIdx.x;
    int stride = gridDim.x * blockDim.x;
    const int T4 = NN * H1 / 4;
    for (int t = i; t < T4; t += stride) {
        int col = (t & 63) * 4;
        float inv = g_rn0[t >> 6];
        float4 o = reinterpret_cast<const float4*>(g_out0)[t];
        float4 rs = reinterpret_cast<const float4*>(g_res0)[t];
        float4 a = *reinterpret_cast<const float4*>(&g_a0[col]);
        float4 b = *reinterpret_cast<const float4*>(&g_b0[col]);
        float h[4];
        h[0] = fmaxf(a.x * (o.x * inv) + b.x, 0.f) + rs.x;
        h[1] = fmaxf(a.y * (o.y * inv) + b.y, 0.f) + rs.y;
        h[2] = fmaxf(a.z * (o.z * inv) + b.z, 0.f) + rs.z;
        h[3] = fmaxf(a.w * (o.w * inv) + b.w, 0.f) + rs.w;
        store_split4(h, &g_Hh[t * 4], &g_Hl[t * 4]);
    }
}

// BN+relu+residual layer 1 + chunked mean-pool; BN coeffs computed inline.
#define BN1_ROWS 16
__global__ void k_bnapply1(const int* __restrict__ batch,
                           const float* __restrict__ g1, const float* __restrict__ be1) {
    __shared__ int bsh[BN1_ROWS];
    int j = threadIdx.x; // 128
    int r0 = blockIdx.x * BN1_ROWS;
    int r1 = min(r0 + BN1_ROWS, NN);
    if (j < BN1_ROWS) bsh[j] = (r0 + j < NN) ? batch[r0 + j] : -1;
    __syncthreads();
    if (r0 >= NN) return;
    float mu = g_sum1[j] / (float)NN;
    float var = g_sq1[j] / (float)NN - mu * mu;
    float a = g1[j] * rsqrtf(var + 1e-5f);
    float b = be1[j] - mu * a;
    float acc = 0.f;
    int cur = bsh[0];
    for (int r = r0; r < r1; r++) {
        int t = r * H2 + j;
        float v = fmaxf(a * g_out1[t] + b, 0.f) + g_tuw[r * 384 + 256 + j];
        int g = bsh[r - r0];
        if (g != cur) {
            atomicAdd(&g_embsum[cur * H2 + j], acc);
            acc = 0.f;
            cur = g;
        }
        acc += v;
    }
    atomicAdd(&g_embsum[cur * H2 + j], acc);
}

// ---------------- classifier: shared-memory, register-blocked ----------------
#define CLS_SMEM ((NG * H2 + NG * 256) * 4)

__global__ __launch_bounds__(256) void k_classifier(
    const float* __restrict__ Wc0, const float* __restrict__ bc0,
    const float* __restrict__ gc0, const float* __restrict__ bec0,
    const float* __restrict__ Wc1, const float* __restrict__ bc1,
    const float* __restrict__ gc1, const float* __restrict__ bec1,
    const float* __restrict__ Wc2, const float* __restrict__ bc2,
    float* __restrict__ out)
{
    extern __shared__ float smf[];
    float* embsh = smf;
    float* z0sh = smf + NG * H2;
    int tid = threadIdx.x;

    for (int t = tid; t < NG * H2; t += 256) {
        int gi = t >> 7;
        float c = fmaxf(g_gcnt[gi], 1.f);
        float v = g_embsum[t] / c;
        embsh[t] = v;
        out[NG * 2 + t] = v;
    }
    __syncthreads();

    {
        int cg = tid & 63;
        int rg = tid >> 6;
        int c = cg * 4;
        int r0 = rg * 16;
        float acc[16][4];
#pragma unroll
        for (int rr = 0; rr < 16; rr++)
#pragma unroll
            for (int qq = 0; qq < 4; qq++) acc[rr][qq] = 0.f;
        for (int k = 0; k < H2; k++) {
            float4 w = *reinterpret_cast<const float4*>(&Wc0[k * 256 + c]);
#pragma unroll
            for (int rr = 0; rr < 16; rr++) {
                float a = embsh[(r0 + rr) * H2 + k];
                acc[rr][0] += a * w.x;
                acc[rr][1] += a * w.y;
                acc[rr][2] += a * w.z;
                acc[rr][3] += a * w.w;
            }
        }
        float4 bi = *reinterpret_cast<const float4*>(&bc0[c]);
#pragma unroll
        for (int rr = 0; rr < 16; rr++) {
            float4 v = make_float4(acc[rr][0] + bi.x, acc[rr][1] + bi.y,
                                   acc[rr][2] + bi.z, acc[rr][3] + bi.w);
            *reinterpret_cast<float4*>(&z0sh[(r0 + rr) * 256 + c]) = v;
        }
    }
    __syncthreads();
    {
        float mu = 0.f, sq = 0.f;
#pragma unroll 8
        for (int r = 0; r < NG; r++) {
            float v = z0sh[r * 256 + tid];
            mu += v;
            sq += v * v;
        }
        mu *= (1.f / NG);
        float var = sq * (1.f / NG) - mu * mu;
        float a = gc0[tid] * rsqrtf(var + 1e-5f);
        float b = bec0[tid] - mu * a;
#pragma unroll 8
        for (int r = 0; r < NG; r++)
            z0sh[r * 256 + tid] = fmaxf(a * z0sh[r * 256 + tid] + b, 0.f);
    }
    __syncthreads();

    {
        int cg = tid & 31;
        int rg = tid >> 5;
        int c = cg * 4;
        int r0 = rg * 8;
        float acc[8][4];
#pragma unroll
        for (int rr = 0; rr < 8; rr++)
#pragma unroll
            for (int qq = 0; qq < 4; qq++) acc[rr][qq] = 0.f;
        for (int k = 0; k < 256; k++) {
            float4 w = *reinterpret_cast<const float4*>(&Wc1[k * 128 + c]);
#pragma unroll
            for (int rr = 0; rr < 8; rr++) {
                float a = z0sh[(r0 + rr) * 256 + k];
                acc[rr][0] += a * w.x;
                acc[rr][1] += a * w.y;
                acc[rr][2] += a * w.z;
                acc[rr][3] += a * w.w;
            }
        }
        float4 bi = *reinterpret_cast<const float4*>(&bc1[c]);
#pragma unroll
        for (int rr = 0; rr < 8; rr++) {
            float4 v = make_float4(acc[rr][0] + bi.x, acc[rr][1] + bi.y,
                                   acc[rr][2] + bi.z, acc[rr][3] + bi.w);
            *reinterpret_cast<float4*>(&embsh[(r0 + rr) * 128 + c]) = v;
        }
    }
    __syncthreads();
    if (tid < 128) {
        float mu = 0.f, sq = 0.f;
#pragma unroll 8
        for (int r = 0; r < NG; r++) {
            float v = embsh[r * 128 + tid];
            mu += v;
            sq += v * v;
        }
        mu *= (1.f / NG);
        float var = sq * (1.f / NG) - mu * mu;
        float a = gc1[tid] * rsqrtf(var + 1e-5f);
        float b = bec1[tid] - mu * a;
#pragma unroll 8
        for (int r = 0; r < NG; r++)
            embsh[r * 128 + tid] = fmaxf(a * embsh[r * 128 + tid] + b, 0.f);
    }
    __syncthreads();

    if (tid < NG * 2) {
        int gi = tid >> 1;
        int c = tid & 1;
        float acc = bc2[c];
        for (int k = 0; k < 128; k++) acc += embsh[gi * 128 + k] * Wc2[k * 2 + c];
        out[gi * 2 + c] = acc;
    }
}

// ---------------- launch ----------------
extern "C" void kernel_launch(void* const* d_in, const int* in_sizes, int n_in,
                              void* d_out, int out_size) {
    const float* x    = (const float*)d_in[0];
    const int*   ei   = (const int*)d_in[1];
    const int*   batch= (const int*)d_in[2];
    const float* Wl0  = (const float*)d_in[3];
    const float* bl0  = (const float*)d_in[4];
    const float* Wr0  = (const float*)d_in[5];
    const float* g0   = (const float*)d_in[6];
    const float* be0  = (const float*)d_in[7];
    const float* Wl1  = (const float*)d_in[8];
    const float* bl1  = (const float*)d_in[9];
    const float* Wr1  = (const float*)d_in[10];
    const float* g1   = (const float*)d_in[11];
    const float* be1  = (const float*)d_in[12];
    const float* Wp0  = (const float*)d_in[13];
    const float* bp0  = (const float*)d_in[14];
    const float* Wp1  = (const float*)d_in[15];
    const float* bp1  = (const float*)d_in[16];
    const float* Wc0  = (const float*)d_in[17];
    const float* bc0  = (const float*)d_in[18];
    const float* gc0  = (const float*)d_in[19];
    const float* bec0 = (const float*)d_in[20];
    const float* Wc1  = (const float*)d_in[21];
    const float* bc1  = (const float*)d_in[22];
    const float* gc1  = (const float*)d_in[23];
    const float* bec1 = (const float*)d_in[24];
    const float* Wc2  = (const float*)d_in[25];
    const float* bc2  = (const float*)d_in[26];
    float* out = (float*)d_out;

    cudaFuncSetAttribute(k_gemm_bf16, cudaFuncAttributeMaxDynamicSharedMemorySize, SMEM_BYTES);
    cudaFuncSetAttribute(k_classifier, cudaFuncAttributeMaxDynamicSharedMemorySize, CLS_SMEM);

    const int MB = (NN + 127) / 128;  // 391

    // CSR build (+weight prep fused)
    k_zero<<<256, 256>>>();
    k_combo<<<3125, 256>>>(ei, batch, Wl0, Wr0, Wp0, Wl1, Wr1, Wp1, bl1, bp1);
    k_scan_a<<<SCAN_BLKS, 256>>>();
    k_scan_b<<<1, 256>>>();
    k_fill<<<3125, 256>>>(ei);

    // layer 0
    k_agg0<<<2048, 256>>>(x);
    k_gemm_bf16<<<dim3(2, MB), 256, SMEM_BYTES>>>(0, bl0);
    k_gemm_bf16<<<dim3(2, MB), 256, SMEM_BYTES>>>(1, bp0);
    k_norm_stats0<<<1024, 256>>>();
    k_bnprep0<<<1, 256>>>(g0, be0);
    k_bnapply0<<<4096, 256>>>();

    // layer 1 (colstats fused into agg1)
    k_gemm_bf16<<<dim3(3, MB), 256, SMEM_BYTES>>>(2, nullptr);
    k_agg1<<<2048, 256>>>();

    // pool (BN coeffs inlined) + classifier
    k_bnapply1<<<(NN + BN1_ROWS - 1) / BN1_ROWS, 128>>>(batch, g1, be1);
    k_classifier<<<1, 256, CLS_SMEM>>>(Wc0, bc0, gc0, bec0, Wc1, bc1, gc1, bec1, Wc2, bc2, out);
}

// round 15
// speedup vs baseline: 1.5097x; 1.5097x over previous
#include <cuda_runtime.h>
#include <cuda_bf16.h>
#include <cstdint>
#include <stdint.h>
#include <math.h>

#define NN 50000
#define EE 800000
#define DIN 128
#define H1 256
#define H2 128
#define NG 64
#define SCAN_BLKS 196

// ---------------- device scratch (static, allocation-free) ----------------
__device__ int   g_deg[NN];
__device__ int   g_rowptr[NN + 1];   // LOCAL (per-256-block) exclusive scan; +g_boff[blk] = absolute
__device__ int   g_cur[NN];          // local cursor; +g_boff at use
__device__ int   g_csrc[EE];
__device__ int   g_bsum[256];
__device__ int   g_boff[256];

// bf16-split activation buffers
__device__ __nv_bfloat16 g_A0h[NN * 256];   // cols 0-127: mean0, 128-255: x
__device__ __nv_bfloat16 g_A0l[NN * 256];
__device__ __nv_bfloat16 g_Hh[NN * 256];    // h (layer-0 output)
__device__ __nv_bfloat16 g_Hl[NN * 256];

// bf16-split weights (prepped each call), [K][N] row-major
__device__ __nv_bfloat16 g_W0h[256 * 256];
__device__ __nv_bfloat16 g_W0l[256 * 256];
__device__ __nv_bfloat16 g_Wp0h[128 * 256];
__device__ __nv_bfloat16 g_Wp0l[128 * 256];
__device__ __nv_bfloat16 g_W1h[256 * 384];
__device__ __nv_bfloat16 g_W1l[256 * 384];
__device__ float g_bias1[384];

// fp32 intermediates
__device__ float g_out0[NN * H1];
__device__ float g_res0[NN * H1];
__device__ float g_rn0[NN];          // per-row inv L2 norm of out0
__device__ float g_tuw[NN * 384];   // 0-127: t, 128-255: u, 256-383: res1
__device__ float g_out1[NN * H2];
__device__ float g_sum0[H1];
__device__ float g_sq0[H1];
__device__ float g_sum1[H2];
__device__ float g_sq1[H2];
__device__ float g_a0[H1];
__device__ float g_b0[H1];
__device__ float g_embsum[NG * H2];
__device__ float g_gcnt[NG];

__device__ __forceinline__ void split_bf16(float v, __nv_bfloat16& h, __nv_bfloat16& l) {
    h = __float2bfloat16(v);
    l = __float2bfloat16(v - __bfloat162float(h));
}

__device__ __forceinline__ void store_split4(const float* v, __nv_bfloat16* ph, __nv_bfloat16* pl) {
    union { __nv_bfloat16 b[4]; uint2 u; } Hh, Ll;
#pragma unroll
    for (int k = 0; k < 4; k++) split_bf16(v[k], Hh.b[k], Ll.b[k]);
    *reinterpret_cast<uint2*>(ph) = Hh.u;
    *reinterpret_cast<uint2*>(pl) = Ll.u;
}

// ---------------- init ----------------
__global__ void k_zero() {
    int i = blockIdx.x * blockDim.x + threadIdx.x;
    int stride = gridDim.x * blockDim.x;
    for (int t = i; t < NN; t += stride) g_deg[t] = 0;
    for (int t = i; t < H1; t += stride) { g_sum0[t] = 0.f; g_sq0[t] = 0.f; }
    for (int t = i; t < H2; t += stride) { g_sum1[t] = 0.f; g_sq1[t] = 0.f; }
    for (int t = i; t < NG * H2; t += stride) g_embsum[t] = 0.f;
    for (int t = i; t < NG; t += stride) g_gcnt[t] = 0.f;
}

// fused: edge-dst degree count + per-graph node count + weight prep
__global__ void k_combo(const int* __restrict__ ei, const int* __restrict__ batch,
                        const float* __restrict__ Wl0, const float* __restrict__ Wr0,
                        const float* __restrict__ Wp0,
                        const float* __restrict__ Wl1, const float* __restrict__ Wr1,
                        const float* __restrict__ Wp1,
                        const float* __restrict__ bl1, const float* __restrict__ bp1) {
    const int* dst = ei + EE;
    int i = blockIdx.x * blockDim.x + threadIdx.x;
    int stride = gridDim.x * blockDim.x;
    for (int e = i; e < EE; e += stride) atomicAdd(&g_deg[dst[e]], 1);
    for (int t = i; t < NN; t += stride) atomicAdd(&g_gcnt[batch[t]], 1.f);

    const int T0 = 256 * 256;
    const int T1 = 128 * 256;
    const int T2 = 256 * 384;
    for (int t = i; t < T0 + T1 + T2; t += stride) {
        if (t < T0) {
            int r = t >> 8;
            int c = t & 255;
            float v = (r < 128) ? Wl0[r * 256 + c] : Wr0[(r - 128) * 256 + c];
            split_bf16(v, g_W0h[t], g_W0l[t]);
        } else if (t < T0 + T1) {
            int j = t - T0;
            split_bf16(Wp0[j], g_Wp0h[j], g_Wp0l[j]);
        } else {
            int j = t - T0 - T1;
            int r = j / 384;
            int c = j % 384;
            float v;
            if (c < 128) v = Wl1[r * 128 + c];
            else if (c < 256) v = Wr1[r * 128 + (c - 128)];
            else v = Wp1[r * 128 + (c - 256)];
            split_bf16(v, g_W1h[j], g_W1l[j]);
        }
    }
    for (int t = i; t < 384; t += stride) {
        float v;
        if (t < 128) v = 0.f;
        else if (t < 256) v = bl1[t - 128];
        else v = bp1[t - 256];
        g_bias1[t] = v;
    }
}

// per-block exclusive scan of deg; writes LOCAL excl to rowptr AND cur; block totals to g_bsum
__global__ void k_scan_a() {
    __shared__ int ws[8];
    int tid = threadIdx.x;
    int lane = tid & 31;
    int w = tid >> 5;
    int idx = blockIdx.x * 256 + tid;
    int v = (idx < NN) ? g_deg[idx] : 0;
    int s = v;
#pragma unroll
    for (int o = 1; o < 32; o <<= 1) {
        int n = __shfl_up_sync(0xffffffffu, s, o);
        if (lane >= o) s += n;
    }
    if (lane == 31) ws[w] = s;
    __syncthreads();
    if (tid < 8) {
        int t = ws[tid];
#pragma unroll
        for (int o = 1; o < 8; o <<= 1) {
            int n = __shfl_up_sync(0xffu, t, o);
            if (tid >= o) t += n;
        }
        ws[tid] = t;
    }
    __syncthreads();
    int incl = s + (w > 0 ? ws[w - 1] : 0);
    int excl = incl - v;
    if (idx < NN) {
        g_rowptr[idx] = excl;
        g_cur[idx] = excl;
    }
    if (tid == 255) g_bsum[blockIdx.x] = incl;
}

// scan block totals -> g_boff
__global__ void k_scan_b() {
    __shared__ int ws[8];
    int tid = threadIdx.x;
    int lane = tid & 31;
    int w = tid >> 5;
    int v = (tid < SCAN_BLKS) ? g_bsum[tid] : 0;
    int s = v;
#pragma unroll
    for (int o = 1; o < 32; o <<= 1) {
        int n = __shfl_up_sync(0xffffffffu, s, o);
        if (lane >= o) s += n;
    }
    if (lane == 31) ws[w] = s;
    __syncthreads();
    if (tid < 8) {
        int t = ws[tid];
#pragma unroll
        for (int o = 1; o < 8; o <<= 1) {
            int n = __shfl_up_sync(0xffu, t, o);
            if (tid >= o) t += n;
        }
        ws[tid] = t;
    }
    __syncthreads();
    int incl = s + (w > 0 ? ws[w - 1] : 0);
    if (tid < SCAN_BLKS) g_boff[tid] = incl - v;
    if (tid == SCAN_BLKS - 1) g_rowptr[NN] = v;
}

__global__ void k_fill(const int* __restrict__ ei) {
    const int* src = ei;
    const int* dst = ei + EE;
    int i = blockIdx.x * blockDim.x + threadIdx.x;
    int stride = gridDim.x * blockDim.x;
    for (int e = i; e < EE; e += stride) {
        int d = dst[e];
        int slot = atomicAdd(&g_cur[d], 1) + g_boff[d >> 8];
        g_csrc[slot] = src[e];
    }
}

// ---------------- aggregation (warp per node; rowptr is local + boff) ----------------
__global__ void k_agg0(const float* __restrict__ x) {
    int gw = (blockIdx.x * blockDim.x + threadIdx.x) >> 5;
    int lane = threadIdx.x & 31;
    int nw = (gridDim.x * blockDim.x) >> 5;
    for (int r = gw; r < NN; r += nw) {
        int s = g_rowptr[r] + g_boff[r >> 8];
        int e = g_rowptr[r + 1] + g_boff[(r + 1) >> 8];
        float4 acc = make_float4(0.f, 0.f, 0.f, 0.f);
        for (int p = s; p < e; p += 32) {
            int cnt = min(e - p, 32);
            int myidx = (lane < cnt) ? g_csrc[p + lane] : 0;
#pragma unroll 4
            for (int q = 0; q < cnt; q++) {
                int nbr = __shfl_sync(0xffffffffu, myidx, q);
                float4 xv = *reinterpret_cast<const float4*>(&x[nbr * DIN + lane * 4]);
                acc.x += xv.x; acc.y += xv.y; acc.z += xv.z; acc.w += xv.w;
            }
        }
        float inv = 1.f / (float)max(e - s, 1);
        float mv[4] = {acc.x * inv, acc.y * inv, acc.z * inv, acc.w * inv};
        store_split4(mv, &g_A0h[r * 256 + lane * 4], &g_A0l[r * 256 + lane * 4]);
        float4 xr = *reinterpret_cast<const float4*>(&x[r * DIN + lane * 4]);
        float xv4[4] = {xr.x, xr.y, xr.z, xr.w};
        store_split4(xv4, &g_A0h[r * 256 + 128 + lane * 4], &g_A0l[r * 256 + 128 + lane * 4]);
    }
}

// layer 1: aggregate t, add u, row L2-normalize -> out1 (NO fused stats —
// long-lived stat accumulators across this loop proved catastrophic in R14).
__global__ void k_agg1() {
    int gw = (blockIdx.x * blockDim.x + threadIdx.x) >> 5;
    int lane = threadIdx.x & 31;
    int nw = (gridDim.x * blockDim.x) >> 5;
    for (int r = gw; r < NN; r += nw) {
        int s = g_rowptr[r] + g_boff[r >> 8];
        int e = g_rowptr[r + 1] + g_boff[(r + 1) >> 8];
        float4 acc = make_float4(0.f, 0.f, 0.f, 0.f);
        for (int p = s; p < e; p += 32) {
            int cnt = min(e - p, 32);
            int myidx = (lane < cnt) ? g_csrc[p + lane] : 0;
#pragma unroll 4
            for (int q = 0; q < cnt; q++) {
                int nbr = __shfl_sync(0xffffffffu, myidx, q);
                float4 tv = *reinterpret_cast<const float4*>(&g_tuw[nbr * 384 + lane * 4]);
                acc.x += tv.x; acc.y += tv.y; acc.z += tv.z; acc.w += tv.w;
            }
        }
        float invd = 1.f / (float)max(e - s, 1);
        float4 uv = *reinterpret_cast<const float4*>(&g_tuw[r * 384 + 128 + lane * 4]);
        float4 v;
        v.x = acc.x * invd + uv.x;
        v.y = acc.y * invd + uv.y;
        v.z = acc.z * invd + uv.z;
        v.w = acc.w * invd + uv.w;
        float q = v.x * v.x + v.y * v.y + v.z * v.z + v.w * v.w;
#pragma unroll
        for (int o = 16; o > 0; o >>= 1) q += __shfl_xor_sync(0xffffffffu, q, o);
        float inv = 1.f / fmaxf(sqrtf(q), 1e-12f);
        v.x *= inv; v.y *= inv; v.z *= inv; v.w *= inv;
        *reinterpret_cast<float4*>(&g_out1[r * H2 + lane * 4]) = v;
    }
}

// ---------------- bf16-split tensor-core GEMM (R5/R9, proven — UNTOUCHED) ----------------
#define A_ST 40
#define B_ST 136
#define A_STAGE_B (128 * A_ST * 2)
#define B_STAGE_B (32 * B_ST * 2)
#define SM_AL_OFF (2 * A_STAGE_B)
#define SM_BH_OFF (4 * A_STAGE_B)
#define SMEM_BYTES (SM_BH_OFF + 4 * B_STAGE_B)

__device__ __forceinline__ void cp16(unsigned int dst, const void* src, bool p) {
    int sz = p ? 16 : 0;
    asm volatile("cp.async.cg.shared.global [%0], [%1], 16, %2;\n"
                 :: "r"(dst), "l"(src), "r"(sz));
}
__device__ __forceinline__ void ldsm4(unsigned int* r, unsigned int a) {
    asm volatile("ldmatrix.sync.aligned.m8n8.x4.shared.b16 {%0,%1,%2,%3}, [%4];"
                 : "=r"(r[0]), "=r"(r[1]), "=r"(r[2]), "=r"(r[3]) : "r"(a));
}
__device__ __forceinline__ void ldsm4t(unsigned int* r, unsigned int a) {
    asm volatile("ldmatrix.sync.aligned.m8n8.x4.trans.shared.b16 {%0,%1,%2,%3}, [%4];"
                 : "=r"(r[0]), "=r"(r[1]), "=r"(r[2]), "=r"(r[3]) : "r"(a));
}
__device__ __forceinline__ void mma_bf16(float* d, const unsigned int* a, const unsigned int* b) {
    asm volatile("mma.sync.aligned.m16n8k16.row.col.f32.bf16.bf16.f32 "
                 "{%0,%1,%2,%3}, {%4,%5,%6,%7}, {%8,%9}, {%0,%1,%2,%3};"
                 : "+f"(d[0]), "+f"(d[1]), "+f"(d[2]), "+f"(d[3])
                 : "r"(a[0]), "r"(a[1]), "r"(a[2]), "r"(a[3]), "r"(b[0]), "r"(b[1]));
}

__device__ __forceinline__ void gemm_load_stage(
    unsigned int sbase, int tid, int row0, int k0, int stage,
    const __nv_bfloat16* Ah, const __nv_bfloat16* Al, int lda,
    const __nv_bfloat16* Bh, const __nv_bfloat16* Bl, int ldb, int col0)
{
#pragma unroll
    for (int i = 0; i < 2; i++) {
        int c = tid + i * 256;
        int row = c >> 2;
        int seg = c & 3;
        int gr = row0 + row;
        bool p = gr < NN;
        size_t goff = (size_t)(p ? gr : 0) * lda + k0 + seg * 8;
        unsigned int d = sbase + stage * A_STAGE_B + (unsigned int)(row * A_ST + seg * 8) * 2;
        cp16(d, Ah + goff, p);
        cp16(d + SM_AL_OFF, Al + goff, p);
    }
#pragma unroll
    for (int i = 0; i < 2; i++) {
        int c = tid + i * 256;
        int row = c >> 4;
        int seg = c & 15;
        size_t goff = (size_t)(k0 + row) * ldb + col0 + seg * 8;
        unsigned int d = sbase + SM_BH_OFF + stage * B_STAGE_B + (unsigned int)(row * B_ST + seg * 8) * 2;
        cp16(d, Bh + goff, true);
        cp16(d + 2 * B_STAGE_B, Bl + goff, true);
    }
    asm volatile("cp.async.commit_group;\n" ::: "memory");
}

// mode 0: out0  = A0 @ W0  (K=256, ldb=256, ldc=256)
// mode 1: res0  = x  @ Wp0 (K=128, ldb=256, ldc=256)
// mode 2: tuw   = H  @ W1  (K=256, ldb=384, ldc=384)
__global__ __launch_bounds__(256) void k_gemm_bf16(int mode, const float* __restrict__ bias_in) {
    extern __shared__ __align__(16) char sm[];
    const int tid = threadIdx.x;
    const int lane = tid & 31;
    const int warp = tid >> 5;
    const int wm = warp & 3;
    const int wn = warp >> 2;
    const int row0 = blockIdx.y * 128;
    const int col0 = blockIdx.x * 128;
    unsigned int sbase = (unsigned int)__cvta_generic_to_shared(sm);

    const __nv_bfloat16* Ah;
    const __nv_bfloat16* Al;
    const __nv_bfloat16* Bh;
    const __nv_bfloat16* Bl;
    const float* bias;
    float* C;
    int lda, ldb, ldc, K;
    if (mode == 0) {
        Ah = g_A0h; Al = g_A0l; lda = 256; K = 256;
        Bh = g_W0h; Bl = g_W0l; ldb = 256;
        bias = bias_in; C = g_out0; ldc = 256;
    } else if (mode == 1) {
        Ah = g_A0h + 128; Al = g_A0l + 128; lda = 256; K = 128;
        Bh = g_Wp0h; Bl = g_Wp0l; ldb = 256;
        bias = bias_in; C = g_res0; ldc = 256;
    } else {
        Ah = g_Hh; Al = g_Hl; lda = 256; K = 256;
        Bh = g_W1h; Bl = g_W1l; ldb = 384;
        bias = g_bias1; C = g_tuw; ldc = 384;
    }

    float acc[2][8][4];
#pragma unroll
    for (int i = 0; i < 2; i++) {
#pragma unroll
        for (int j = 0; j < 8; j++) {
#pragma unroll
            for (int q = 0; q < 4; q++) acc[i][j][q] = 0.f;
        }
    }

    const int S = K / 32;
    gemm_load_stage(sbase, tid, row0, 0, 0, Ah, Al, lda, Bh, Bl, ldb, col0);

    for (int s = 0; s < S; s++) {
        if (s + 1 < S) {
            gemm_load_stage(sbase, tid, row0, (s + 1) * 32, (s + 1) & 1, Ah, Al, lda, Bh, Bl, ldb, col0);
            asm volatile("cp.async.wait_group 1;\n" ::: "memory");
        } else {
            asm volatile("cp.async.wait_group 0;\n" ::: "memory");
        }
        __syncthreads();
        int stage = s & 1;
#pragma unroll
        for (int kk = 0; kk < 32; kk += 16) {
            unsigned int aH[2][4], aL[2][4];
#pragma unroll
            for (int mi = 0; mi < 2; mi++) {
                int r = wm * 32 + mi * 16 + (lane & 15);
                int cA = kk + ((lane >> 4) << 3);
                unsigned int ad = sbase + stage * A_STAGE_B + (unsigned int)(r * A_ST + cA) * 2;
                ldsm4(aH[mi], ad);
                ldsm4(aL[mi], ad + SM_AL_OFF);
            }
#pragma unroll
            for (int g = 0; g < 4; g++) {
                unsigned int bH[4], bL[4];
                int rB = kk + (lane & 15);
                int cB = wn * 64 + g * 16 + ((lane >> 4) << 3);
                unsigned int bd = sbase + SM_BH_OFF + stage * B_STAGE_B + (unsigned int)(rB * B_ST + cB) * 2;
                ldsm4t(bH, bd);
                ldsm4t(bL, bd + 2 * B_STAGE_B);
#pragma unroll
                for (int mi = 0; mi < 2; mi++) {
                    mma_bf16(acc[mi][2 * g], aH[mi], &bH[0]);
                    mma_bf16(acc[mi][2 * g], aL[mi], &bH[0]);
                    mma_bf16(acc[mi][2 * g], aH[mi], &bL[0]);
                    mma_bf16(acc[mi][2 * g + 1], aH[mi], &bH[2]);
                    mma_bf16(acc[mi][2 * g + 1], aL[mi], &bH[2]);
                    mma_bf16(acc[mi][2 * g + 1], aH[mi], &bL[2]);
                }
            }
        }
        __syncthreads();
    }

#pragma unroll
    for (int mi = 0; mi < 2; mi++) {
        int r0 = row0 + wm * 32 + mi * 16 + (lane >> 2);
#pragma unroll
        for (int nj = 0; nj < 8; nj++) {
            int c = col0 + wn * 64 + nj * 8 + 2 * (lane & 3);
            float b0 = bias[c];
            float b1 = bias[c + 1];
            if (r0 < NN) {
                float2 v = make_float2(acc[mi][nj][0] + b0, acc[mi][nj][1] + b1);
                *reinterpret_cast<float2*>(C + (size_t)r0 * ldc + c) = v;
            }
            if (r0 + 8 < NN) {
                float2 v = make_float2(acc[mi][nj][2] + b0, acc[mi][nj][3] + b1);
                *reinterpret_cast<float2*>(C + (size_t)(r0 + 8) * ldc + c) = v;
            }
        }
    }
}

// ---------------- row L2-norm + column stats (layer 0), warp per row ----------------
__global__ void k_norm_stats0() {
    __shared__ float ssum[256];
    __shared__ float ssq[256];
    int tid = threadIdx.x;
    int lane = tid & 31;
    int gw = (blockIdx.x * blockDim.x + tid) >> 5;
    int nw = (gridDim.x * blockDim.x) >> 5;
    ssum[tid] = 0.f;
    ssq[tid] = 0.f;
    __syncthreads();
    float s[8], q[8];
#pragma unroll
    for (int k = 0; k < 8; k++) { s[k] = 0.f; q[k] = 0.f; }
    for (int r = gw; r < NN; r += nw) {
        float4 v0 = *reinterpret_cast<const float4*>(&g_out0[r * H1 + lane * 8]);
        float4 v1 = *reinterpret_cast<const float4*>(&g_out0[r * H1 + lane * 8 + 4]);
        float t = v0.x * v0.x + v0.y * v0.y + v0.z * v0.z + v0.w * v0.w
                + v1.x * v1.x + v1.y * v1.y + v1.z * v1.z + v1.w * v1.w;
#pragma unroll
        for (int o = 16; o > 0; o >>= 1) t += __shfl_xor_sync(0xffffffffu, t, o);
        float inv = 1.f / fmaxf(sqrtf(t), 1e-12f);
        if (lane == 0) g_rn0[r] = inv;
        float v[8] = {v0.x * inv, v0.y * inv, v0.z * inv, v0.w * inv,
                      v1.x * inv, v1.y * inv, v1.z * inv, v1.w * inv};
#pragma unroll
        for (int k = 0; k < 8; k++) { s[k] += v[k]; q[k] += v[k] * v[k]; }
    }
#pragma unroll
    for (int k = 0; k < 8; k++) {
        atomicAdd(&ssum[lane * 8 + k], s[k]);
        atomicAdd(&ssq[lane * 8 + k], q[k]);
    }
    __syncthreads();
    atomicAdd(&g_sum0[tid], ssum[tid]);
    atomicAdd(&g_sq0[tid], ssq[tid]);
}

__global__ void k_colstats1() {
    int j = threadIdx.x; // 128
    float s = 0.f, q = 0.f;
    for (int r = blockIdx.x; r < NN; r += gridDim.x) {
        float v = g_out1[r * H2 + j];
        s += v;
        q += v * v;
    }
    atomicAdd(&g_sum1[j], s);
    atomicAdd(&g_sq1[j], q);
}

// bnprep for layer 0 only
__global__ void k_bnprep0(const float* __restrict__ g, const float* __restrict__ be) {
    int j = threadIdx.x;
    if (j < H1) {
        float mu = g_sum0[j] / (float)NN;
        float var = g_sq0[j] / (float)NN - mu * mu;
        float s = g[j] * rsqrtf(var + 1e-5f);
        g_a0[j] = s;
        g_b0[j] = be[j] - mu * s;
    }
}

// BN + relu + residual layer 0; applies row inv-norm from g_rn0 on the fly.
__global__ void k_bnapply0() {
    int i = blockIdx.x * blockDim.x + threadIdx.x;
    int stride = gridDim.x * blockDim.x;
    const int T4 = NN * H1 / 4;
    for (int t = i; t < T4; t += stride) {
        int col = (t & 63) * 4;
        float inv = g_rn0[t >> 6];
        float4 o = reinterpret_cast<const float4*>(g_out0)[t];
        float4 rs = reinterpret_cast<const float4*>(g_res0)[t];
        float4 a = *reinterpret_cast<const float4*>(&g_a0[col]);
        float4 b = *reinterpret_cast<const float4*>(&g_b0[col]);
        float h[4];
        h[0] = fmaxf(a.x * (o.x * inv) + b.x, 0.f) + rs.x;
        h[1] = fmaxf(a.y * (o.y * inv) + b.y, 0.f) + rs.y;
        h[2] = fmaxf(a.z * (o.z * inv) + b.z, 0.f) + rs.z;
        h[3] = fmaxf(a.w * (o.w * inv) + b.w, 0.f) + rs.w;
        store_split4(h, &g_Hh[t * 4], &g_Hl[t * 4]);
    }
}

// BN+relu+residual layer 1 + chunked mean-pool; BN coeffs computed inline.
#define BN1_ROWS 16
__global__ void k_bnapply1(const int* __restrict__ batch,
                           const float* __restrict__ g1, const float* __restrict__ be1) {
    __shared__ int bsh[BN1_ROWS];
    int j = threadIdx.x; // 128
    int r0 = blockIdx.x * BN1_ROWS;
    int r1 = min(r0 + BN1_ROWS, NN);
    if (j < BN1_ROWS) bsh[j] = (r0 + j < NN) ? batch[r0 + j] : -1;
    __syncthreads();
    if (r0 >= NN) return;
    float mu = g_sum1[j] / (float)NN;
    float var = g_sq1[j] / (float)NN - mu * mu;
    float a = g1[j] * rsqrtf(var + 1e-5f);
    float b = be1[j] - mu * a;
    float acc = 0.f;
    int cur = bsh[0];
    for (int r = r0; r < r1; r++) {
        int t = r * H2 + j;
        float v = fmaxf(a * g_out1[t] + b, 0.f) + g_tuw[r * 384 + 256 + j];
        int g = bsh[r - r0];
        if (g != cur) {
            atomicAdd(&g_embsum[cur * H2 + j], acc);
            acc = 0.f;
            cur = g;
        }
        acc += v;
    }
    atomicAdd(&g_embsum[cur * H2 + j], acc);
}

// ---------------- classifier: shared-memory, register-blocked ----------------
#define CLS_SMEM ((NG * H2 + NG * 256) * 4)

__global__ __launch_bounds__(256) void k_classifier(
    const float* __restrict__ Wc0, const float* __restrict__ bc0,
    const float* __restrict__ gc0, const float* __restrict__ bec0,
    const float* __restrict__ Wc1, const float* __restrict__ bc1,
    const float* __restrict__ gc1, const float* __restrict__ bec1,
    const float* __restrict__ Wc2, const float* __restrict__ bc2,
    float* __restrict__ out)
{
    extern __shared__ float smf[];
    float* embsh = smf;
    float* z0sh = smf + NG * H2;
    int tid = threadIdx.x;

    for (int t = tid; t < NG * H2; t += 256) {
        int gi = t >> 7;
        float c = fmaxf(g_gcnt[gi], 1.f);
        float v = g_embsum[t] / c;
        embsh[t] = v;
        out[NG * 2 + t] = v;
    }
    __syncthreads();

    {
        int cg = tid & 63;
        int rg = tid >> 6;
        int c = cg * 4;
        int r0 = rg * 16;
        float acc[16][4];
#pragma unroll
        for (int rr = 0; rr < 16; rr++)
#pragma unroll
            for (int qq = 0; qq < 4; qq++) acc[rr][qq] = 0.f;
        for (int k = 0; k < H2; k++) {
            float4 w = *reinterpret_cast<const float4*>(&Wc0[k * 256 + c]);
#pragma unroll
            for (int rr = 0; rr < 16; rr++) {
                float a = embsh[(r0 + rr) * H2 + k];
                acc[rr][0] += a * w.x;
                acc[rr][1] += a * w.y;
                acc[rr][2] += a * w.z;
                acc[rr][3] += a * w.w;
            }
        }
        float4 bi = *reinterpret_cast<const float4*>(&bc0[c]);
#pragma unroll
        for (int rr = 0; rr < 16; rr++) {
            float4 v = make_float4(acc[rr][0] + bi.x, acc[rr][1] + bi.y,
                                   acc[rr][2] + bi.z, acc[rr][3] + bi.w);
            *reinterpret_cast<float4*>(&z0sh[(r0 + rr) * 256 + c]) = v;
        }
    }
    __syncthreads();
    {
        float mu = 0.f, sq = 0.f;
#pragma unroll 8
        for (int r = 0; r < NG; r++) {
            float v = z0sh[r * 256 + tid];
            mu += v;
            sq += v * v;
        }
        mu *= (1.f / NG);
        float var = sq * (1.f / NG) - mu * mu;
        float a = gc0[tid] * rsqrtf(var + 1e-5f);
        float b = bec0[tid] - mu * a;
#pragma unroll 8
        for (int r = 0; r < NG; r++)
            z0sh[r * 256 + tid] = fmaxf(a * z0sh[r * 256 + tid] + b, 0.f);
    }
    __syncthreads();

    {
        int cg = tid & 31;
        int rg = tid >> 5;
        int c = cg * 4;
        int r0 = rg * 8;
        float acc[8][4];
#pragma unroll
        for (int rr = 0; rr < 8; rr++)
#pragma unroll
            for (int qq = 0; qq < 4; qq++) acc[rr][qq] = 0.f;
        for (int k = 0; k < 256; k++) {
            float4 w = *reinterpret_cast<const float4*>(&Wc1[k * 128 + c]);
#pragma unroll
            for (int rr = 0; rr < 8; rr++) {
                float a = z0sh[(r0 + rr) * 256 + k];
                acc[rr][0] += a * w.x;
                acc[rr][1] += a * w.y;
                acc[rr][2] += a * w.z;
                acc[rr][3] += a * w.w;
            }
        }
        float4 bi = *reinterpret_cast<const float4*>(&bc1[c]);
#pragma unroll
        for (int rr = 0; rr < 8; rr++) {
            float4 v = make_float4(acc[rr][0] + bi.x, acc[rr][1] + bi.y,
                                   acc[rr][2] + bi.z, acc[rr][3] + bi.w);
            *reinterpret_cast<float4*>(&embsh[(r0 + rr) * 128 + c]) = v;
        }
    }
    __syncthreads();
    if (tid < 128) {
        float mu = 0.f, sq = 0.f;
#pragma unroll 8
        for (int r = 0; r < NG; r++) {
            float v = embsh[r * 128 + tid];
            mu += v;
            sq += v * v;
        }
        mu *= (1.f / NG);
        float var = sq * (1.f / NG) - mu * mu;
        float a = gc1[tid] * rsqrtf(var + 1e-5f);
        float b = bec1[tid] - mu * a;
#pragma unroll 8
        for (int r = 0; r < NG; r++)
            embsh[r * 128 + tid] = fmaxf(a * embsh[r * 128 + tid] + b, 0.f);
    }
    __syncthreads();

    if (tid < NG * 2) {
        int gi = tid >> 1;
        int c = tid & 1;
        float acc = bc2[c];
        for (int k = 0; k < 128; k++) acc += embsh[gi * 128 + k] * Wc2[k * 2 + c];
        out[gi * 2 + c] = acc;
    }
}

// ---------------- launch ----------------
extern "C" void kernel_launch(void* const* d_in, const int* in_sizes, int n_in,
                              void* d_out, int out_size) {
    const float* x    = (const float*)d_in[0];
    const int*   ei   = (const int*)d_in[1];
    const int*   batch= (const int*)d_in[2];
    const float* Wl0  = (const float*)d_in[3];
    const float* bl0  = (const float*)d_in[4];
    const float* Wr0  = (const float*)d_in[5];
    const float* g0   = (const float*)d_in[6];
    const float* be0  = (const float*)d_in[7];
    const float* Wl1  = (const float*)d_in[8];
    const float* bl1  = (const float*)d_in[9];
    const float* Wr1  = (const float*)d_in[10];
    const float* g1   = (const float*)d_in[11];
    const float* be1  = (const float*)d_in[12];
    const float* Wp0  = (const float*)d_in[13];
    const float* bp0  = (const float*)d_in[14];
    const float* Wp1  = (const float*)d_in[15];
    const float* bp1  = (const float*)d_in[16];
    const float* Wc0  = (const float*)d_in[17];
    const float* bc0  = (const float*)d_in[18];
    const float* gc0  = (const float*)d_in[19];
    const float* bec0 = (const float*)d_in[20];
    const float* Wc1  = (const float*)d_in[21];
    const float* bc1  = (const float*)d_in[22];
    const float* gc1  = (const float*)d_in[23];
    const float* bec1 = (const float*)d_in[24];
    const float* Wc2  = (const float*)d_in[25];
    const float* bc2  = (const float*)d_in[26];
    float* out = (float*)d_out;

    cudaFuncSetAttribute(k_gemm_bf16, cudaFuncAttributeMaxDynamicSharedMemorySize, SMEM_BYTES);
    cudaFuncSetAttribute(k_classifier, cudaFuncAttributeMaxDynamicSharedMemorySize, CLS_SMEM);

    const int MB = (NN + 127) / 128;  // 391

    // CSR build (+weight prep fused)
    k_zero<<<256, 256>>>();
    k_combo<<<3125, 256>>>(ei, batch, Wl0, Wr0, Wp0, Wl1, Wr1, Wp1, bl1, bp1);
    k_scan_a<<<SCAN_BLKS, 256>>>();
    k_scan_b<<<1, 256>>>();
    k_fill<<<3125, 256>>>(ei);

    // layer 0
    k_agg0<<<2048, 256>>>(x);
    k_gemm_bf16<<<dim3(2, MB), 256, SMEM_BYTES>>>(0, bl0);
    k_gemm_bf16<<<dim3(2, MB), 256, SMEM_BYTES>>>(1, bp0);
    k_norm_stats0<<<1024, 256>>>();
    k_bnprep0<<<1, 256>>>(g0, be0);
    k_bnapply0<<<4096, 256>>>();

    // layer 1
    k_gemm_bf16<<<dim3(3, MB), 256, SMEM_BYTES>>>(2, nullptr);
    k_agg1<<<2048, 256>>>();
    k_colstats1<<<2048, 128>>>();

    // pool (BN coeffs inlined) + classifier
    k_bnapply1<<<(NN + BN1_ROWS - 1) / BN1_ROWS, 128>>>(batch, g1, be1);
    k_classifier<<<1, 256, CLS_SMEM>>>(Wc0, bc0, gc0, bec0, Wc1, bc1, gc1, bec1, Wc2, bc2, out);
}